// round 10
// baseline (speedup 1.0000x reference)
#include <cuda_runtime.h>
#include <stdint.h>

#define Bb 32
#define Nn 512
#define Ll 8
#define Kk 8
#define MS 64
#define SP 68    // shared stride: conflict-free, 16B-aligned rows

// ---------------- scratch (static device globals) ---------------------------
__device__ float  g_M [Bb][MS][MS];      // M natural
__device__ float  g_MT[Bb][MS][MS];      // MT[i][j] = M[j][i]
__device__ float  g_DcolT[Bb][Nn][MS];   // strip D transposed (per column)
__device__ float  g_AcolT[Bb][Nn][MS];
__device__ int8_t g_slotof[Bb][Nn];
__device__ int    g_slots[Bb][MS];
__device__ int8_t g_wflag[Bb][128];      // padded per b
__device__ int    g_m[Bb][32];           // padded per b
__device__ int    g_flagM[Bb];           // maps ready
__device__ int    g_flagMT[Bb];          // M + MT ready
__device__ float  g_sink;

// ---------------- packed f32x2 helpers --------------------------------------
typedef unsigned long long ull;

__device__ __forceinline__ ull pack2(float x) {
    ull r; asm("mov.b64 %0, {%1, %1};" : "=l"(r) : "f"(x)); return r;
}
__device__ __forceinline__ void ffma2(ull& d, ull a, ull b) {
    asm("fma.rn.f32x2 %0, %1, %2, %3;" : "=l"(d) : "l"(a), "l"(b), "l"(d));
}
__device__ __forceinline__ void unpack2(ull v, float& lo, float& hi) {
    asm("mov.b64 {%0, %1}, %2;" : "=f"(lo), "=f"(hi) : "l"(v));
}

// C = A @ B (64x64), 512 threads, 2 rows x 4 cols per thread.
// AT[k][i] = A[i][k]; Bsh[k][j] natural. Conflict-free.
__device__ __forceinline__ void gemmAT512(const float* __restrict__ AT,
                                          const float* __restrict__ Bsh,
                                          float* __restrict__ Csh, int tid) {
    const int i0 = (tid >> 4) * 2;
    const int j0 = (tid & 15) * 4;
    ull a00 = 0, a01 = 0, a10 = 0, a11 = 0;
    #pragma unroll 8
    for (int k = 0; k < 64; k++) {
        float2 aq = *(const float2*)&AT[k * SP + i0];
        ulonglong2 bq = *(const ulonglong2*)&Bsh[k * SP + j0];
        ull p0 = pack2(aq.x), p1 = pack2(aq.y);
        ffma2(a00, p0, bq.x); ffma2(a01, p0, bq.y);
        ffma2(a10, p1, bq.x); ffma2(a11, p1, bq.y);
    }
    ulonglong2 s0; s0.x = a00; s0.y = a01;
    ulonglong2 s1; s1.x = a10; s1.y = a11;
    *(ulonglong2*)&Csh[i0 * SP + j0]       = s0;
    *(ulonglong2*)&Csh[(i0 + 1) * SP + j0] = s1;
}

// ---------------- KA: roles A (setup + corners) + C (strip tiles) ------------
#define KF_SMEM (5 * 64 * SP * 4)
#define NC_BASE 32
#define KA_GRID (NC_BASE + Bb * 8)   // 288 <= 296 resident slots

__global__ void __launch_bounds__(512, 2)
mmf_ka(const float* __restrict__ A, const float* __restrict__ O,
       const int* __restrict__ idx, const int* __restrict__ wav,
       float* __restrict__ out) {
    extern __shared__ float sm[];
    const int bid = blockIdx.x;
    const int tid = threadIdx.x;
    const size_t MAT = (size_t)Bb * Nn * Nn;

    // ======================= ROLE A: per-batch setup ========================
    if (bid < Bb) {
        float* Msh  = sm;
        float* MTsh = sm + 1 * 64 * SP;
        float* BufA = sm + 2 * 64 * SP;   // A_RR
        float* BufB = sm + 3 * 64 * SP;   // Y, then T
        float* BufC = sm + 4 * 64 * SP;   // D_RR

        __shared__ int   slotof[Nn];
        __shared__ int   slots[MS], val[MS], isf[MS], pslot[MS], wflag[MS];
        __shared__ int   mSh;
        __shared__ float OshAll[Ll * MS];

        const int b   = bid;
        const int wid = tid >> 5;
        const int lid = tid & 31;

        slotof[tid] = -1;
        if (tid < MS) { wflag[tid] = 0; slots[tid] = 0; val[tid] = idx[b * MS + tid]; }
        OshAll[tid] = O[(size_t)(tid >> 6) * Bb * MS + (size_t)b * MS + (tid & 63)];
        for (int e = tid; e < 4096; e += 512) {
            int i = e >> 6, j = e & 63;
            Msh[i * SP + j] = (i == j) ? 1.f : 0.f;
        }
        __syncthreads();

        // dedup
        if (tid < MS) {
            const int v = val[tid];
            int fp = MS;
            #pragma unroll 8
            for (int q = MS - 1; q >= 0; q--) if (val[q] == v) fp = q;
            isf[tid] = (fp == tid) ? 1 : 0;
            pslot[tid] = fp;
        }
        __syncthreads();
        if (tid < MS) {
            const int fp = pslot[tid];
            int s = 0;
            #pragma unroll 8
            for (int q = 0; q < MS; q++) s += (q < fp) ? isf[q] : 0;
            pslot[tid] = s;
            if (isf[tid]) { slots[s] = val[tid]; slotof[val[tid]] = s; }
        }
        __syncthreads();
        if (tid < Ll) wflag[slotof[wav[b * Ll + tid]]] = 1;
        if (tid == 256) {
            int m = 0;
            #pragma unroll
            for (int q = 0; q < MS; q++) m += isf[q];
            mSh = m;
            g_m[b][0] = m;
        }
        __syncthreads();

        // publish maps -> flagM
        g_slotof[b][tid] = (int8_t)slotof[tid];
        if (tid < MS) {
            g_slots[b][tid] = slots[tid];
            g_wflag[b][tid] = (int8_t)wflag[tid];
        }
        __threadfence();
        __syncthreads();
        if (tid == 0) *(volatile int*)&g_flagM[b] = 1;

        // warp 0 builds M; warps 1-15 gather A_RR
        if (wid == 0) {
            for (int l = 0; l < Ll; l++) {
                int rsv[Kk];
                #pragma unroll
                for (int j = 0; j < Kk; j++) rsv[j] = pslot[l * Kk + j];
                float acc0[Kk], acc1[Kk];
                #pragma unroll
                for (int i = 0; i < Kk; i++) { acc0[i] = 0.f; acc1[i] = 0.f; }
                #pragma unroll
                for (int j = 0; j < Kk; j++) {
                    const float m0 = Msh[rsv[j] * SP + lid];
                    const float m1 = Msh[rsv[j] * SP + lid + 32];
                    #pragma unroll
                    for (int i = 0; i < Kk; i++) {
                        const float o = OshAll[l * MS + i * Kk + j];
                        acc0[i] += o * m0;
                        acc1[i] += o * m1;
                    }
                }
                __syncwarp();
                #pragma unroll
                for (int i = 0; i < Kk; i++) {
                    Msh[rsv[i] * SP + lid]      = acc0[i];
                    Msh[rsv[i] * SP + lid + 32] = acc1[i];
                }
                __syncwarp();
            }
        } else {
            const int t = tid - 32;
            for (int e = t; e < 4096; e += 480) {
                int i = e >> 6, j = e & 63;
                BufA[i * SP + j] = A[((size_t)b * Nn + slots[i]) * Nn + slots[j]];
            }
        }
        __syncthreads();

        // transpose; publish M + MT -> flagMT
        for (int e = tid; e < 4096; e += 512) {
            int i = e >> 6, j = e & 63;
            MTsh[j * SP + i] = Msh[i * SP + j];
        }
        __syncthreads();
        for (int e = tid; e < 4096; e += 512) {
            int i = e >> 6, j = e & 63;
            g_M[b][i][j]  = Msh[i * SP + j];
            g_MT[b][i][j] = MTsh[i * SP + j];
        }
        __threadfence();
        __syncthreads();
        if (tid == 0) *(volatile int*)&g_flagMT[b] = 1;

        // S1: Y = A_RR @ M^T (A_RR symmetric -> AT = BufA; B = MTsh)
        gemmAT512(BufA, MTsh, BufB, tid);  __syncthreads();

        // S2: F = M @ Y, mask fused -> BufC (=D_RR)
        {
            const int i0 = (tid >> 4) * 2;
            const int j0 = (tid & 15) * 4;
            ull a00 = 0, a01 = 0, a10 = 0, a11 = 0;
            #pragma unroll 8
            for (int k = 0; k < 64; k++) {
                float2 aq = *(const float2*)&MTsh[k * SP + i0];
                ulonglong2 bq = *(const ulonglong2*)&BufB[k * SP + j0];
                ull p0 = pack2(aq.x), p1 = pack2(aq.y);
                ffma2(a00, p0, bq.x); ffma2(a01, p0, bq.y);
                ffma2(a10, p1, bq.x); ffma2(a11, p1, bq.y);
            }
            float f[2][4];
            unpack2(a00, f[0][0], f[0][1]); unpack2(a01, f[0][2], f[0][3]);
            unpack2(a10, f[1][0], f[1][1]); unpack2(a11, f[1][2], f[1][3]);
            #pragma unroll
            for (int r = 0; r < 2; r++) {
                const int i = i0 + r;
                float4 dv;
                float* dp = (float*)&dv;
                #pragma unroll
                for (int q = 0; q < 4; q++) {
                    const int j = j0 + q;
                    float v = f[r][q];
                    if (i != j && (wflag[i] || wflag[j])) v = 0.f;
                    dp[q] = v;
                }
                *(float4*)&BufC[i * SP + j0] = dv;
            }
        }
        __syncthreads();

        // S3: T = D @ M (D symmetric -> AT = BufC; B = Msh) -> BufB
        gemmAT512(BufC, Msh, BufB, tid);  __syncthreads();

        // S4: G2 = M^T @ T -> registers; write corner blocks directly
        {
            const int i0 = (tid >> 4) * 2;
            const int j0 = (tid & 15) * 4;
            ull a00 = 0, a01 = 0, a10 = 0, a11 = 0;
            #pragma unroll 8
            for (int k = 0; k < 64; k++) {
                float2 aq = *(const float2*)&Msh[k * SP + i0];
                ulonglong2 bq = *(const ulonglong2*)&BufB[k * SP + j0];
                ull p0 = pack2(aq.x), p1 = pack2(aq.y);
                ffma2(a00, p0, bq.x); ffma2(a01, p0, bq.y);
                ffma2(a10, p1, bq.x); ffma2(a11, p1, bq.y);
            }
            float g2[2][4];
            unpack2(a00, g2[0][0], g2[0][1]); unpack2(a01, g2[0][2], g2[0][3]);
            unpack2(a10, g2[1][0], g2[1][1]); unpack2(a11, g2[1][2], g2[1][3]);

            // corner writes: rows slots[i], cols slots[j], i,j < m
            const int m = mSh;
            #pragma unroll
            for (int r = 0; r < 2; r++) {
                const int i = i0 + r;
                if (i >= m) continue;
                const size_t rowb = ((size_t)b * Nn + slots[i]) * Nn;
                #pragma unroll
                for (int q = 0; q < 4; q++) {
                    const int j = j0 + q;
                    if (j >= m) continue;
                    const size_t ro = rowb + slots[j];
                    out[ro]           = g2[r][q];            // A_rec
                    out[MAT + ro]     = Msh[i * SP + j];     // right
                    out[2 * MAT + ro] = BufC[i * SP + j];    // D
                }
            }
        }
        return;
    }

    // ================== ROLE C: strip tiles ==================================
    {
        float* MTsh = sm;
        float* Psh  = sm + 1 * 64 * SP;
        float* At   = sm + 2 * 64 * SP;
        float* Dsh  = sm + 3 * 64 * SP;   // first: M natural; then D tile
        float* Esh  = sm + 4 * 64 * SP;

        __shared__ int    slots_s[MS];
        __shared__ int8_t wfl[MS];
        __shared__ int8_t slrow[MS];
        __shared__ int    mS;

        const int t  = bid - NC_BASE;
        const int b  = t >> 3;
        const int c0 = (t & 7) << 6;

        // wait for maps
        if (tid == 0) { while (*(volatile int*)&g_flagM[b] == 0) __nanosleep(100); }
        __syncthreads();
        __threadfence();

        if (tid < MS) {
            slots_s[tid] = g_slots[b][tid];
            slrow[tid]   = g_slotof[b][c0 + tid];
            wfl[tid]     = g_wflag[b][tid];
        }
        if (tid == 0) mS = g_m[b][0];
        __syncthreads();

        // --- overlap with role A: gather tile, right-identity rows, L2 warm
        for (int e = tid; e < 4096; e += 512) {
            int k = e >> 6, c = e & 63;
            At[k * SP + c] = A[((size_t)b * Nn + slots_s[k]) * Nn + c0 + c];
        }
        {
            float acc = 0.f;
            for (int it = 0; it < 16; it++) {
                const int e = it * 512 + tid;
                const int r = e >> 7, lane = e & 127;
                const int i = c0 + r, cc0 = lane * 4;
                const size_t rowbase = ((size_t)b * Nn + i) * Nn + cc0;
                float4 a = __ldg((const float4*)&A[rowbase]);   // warm L2
                acc += a.x + a.w;
                if (slrow[r] < 0) {
                    float4 vr = make_float4(0.f, 0.f, 0.f, 0.f);
                    if (i >= cc0 && i < cc0 + 4) ((float*)&vr)[i - cc0] = 1.f;
                    __stcs((float4*)&out[MAT + rowbase], vr);
                }
            }
            if (acc == 1e38f) g_sink = acc;
        }

        // wait for M + MT
        if (tid == 0) { while (*(volatile int*)&g_flagMT[b] == 0) __nanosleep(100); }
        __syncthreads();
        __threadfence();

        for (int e = tid; e < 4096; e += 512) {
            int i = e >> 6, j = e & 63;
            MTsh[i * SP + j] = g_MT[b][i][j];
            Dsh[i * SP + j]  = g_M[b][i][j];    // M natural (temp)
        }
        __syncthreads();

        // P = M^T diag(~w) M -> Psh (AT = Dsh = M natural, masked; B = Dsh)
        {
            const int i0 = (tid >> 4) * 2;
            const int j0 = (tid & 15) * 4;
            ull y00 = 0, y01 = 0, y10 = 0, y11 = 0;
            #pragma unroll 8
            for (int k = 0; k < 64; k++) {
                const bool wz = (wfl[k] != 0);
                float2 cq = *(const float2*)&Dsh[k * SP + i0];
                ulonglong2 bq = *(const ulonglong2*)&Dsh[k * SP + j0];
                ull q0 = wz ? 0ULL : pack2(cq.x);
                ull q1 = wz ? 0ULL : pack2(cq.y);
                ffma2(y00, q0, bq.x); ffma2(y01, q0, bq.y);
                ffma2(y10, q1, bq.x); ffma2(y11, q1, bq.y);
            }
            ulonglong2 s0; s0.x = y00; s0.y = y01;
            ulonglong2 s1; s1.x = y10; s1.y = y11;
            const int i0b = (tid >> 4) * 2;
            *(ulonglong2*)&Psh[i0b * SP + j0]       = s0;
            *(ulonglong2*)&Psh[(i0b + 1) * SP + j0] = s1;
        }
        __syncthreads();

        // dual GEMM: F = M @ At (AT=MTsh), E = P @ At (P symmetric -> AT=Psh)
        const int i0 = (tid >> 4) * 2;
        const int j0 = (tid & 15) * 4;
        ull x00 = 0, x01 = 0, x10 = 0, x11 = 0;
        ull y00 = 0, y01 = 0, y10 = 0, y11 = 0;
        #pragma unroll 4
        for (int k = 0; k < 64; k++) {
            float2 mq = *(const float2*)&MTsh[k * SP + i0];
            float2 pq = *(const float2*)&Psh[k * SP + i0];
            ulonglong2 bq = *(const ulonglong2*)&At[k * SP + j0];
            ull m0 = pack2(mq.x), m1 = pack2(mq.y);
            ull p0 = pack2(pq.x), p1 = pack2(pq.y);
            ffma2(x00, m0, bq.x); ffma2(x01, m0, bq.y);
            ffma2(x10, m1, bq.x); ffma2(x11, m1, bq.y);
            ffma2(y00, p0, bq.x); ffma2(y01, p0, bq.y);
            ffma2(y10, p1, bq.x); ffma2(y11, p1, bq.y);
        }

        const int s0 = slrow[j0], s1 = slrow[j0 + 1];
        const int s2 = slrow[j0 + 2], s3 = slrow[j0 + 3];
        float f[2][4], e2[2][4];
        unpack2(x00, f[0][0], f[0][1]); unpack2(x01, f[0][2], f[0][3]);
        unpack2(x10, f[1][0], f[1][1]); unpack2(x11, f[1][2], f[1][3]);
        unpack2(y00, e2[0][0], e2[0][1]); unpack2(y01, e2[0][2], e2[0][3]);
        unpack2(y10, e2[1][0], e2[1][1]); unpack2(y11, e2[1][2], e2[1][3]);
        __syncthreads();   // Dsh (M natural) no longer needed

        const int sq[4] = { s0, s1, s2, s3 };
        #pragma unroll
        for (int r = 0; r < 2; r++) {
            const int i = i0 + r;
            const float wz = wfl[i] ? 0.f : 1.f;
            float4 dv, av;
            float* dp = (float*)&dv;
            float* ap = (float*)&av;
            #pragma unroll
            for (int q = 0; q < 4; q++) {
                dp[q] = wz * f[r][q];
                ap[q] = e2[r][q];
            }
            *(float4*)&Dsh[i * SP + j0] = dv;
            *(float4*)&Esh[i * SP + j0] = av;
            if (i < mS) {
                // strip-row outputs for non-R columns only (R columns = role A)
                const size_t base = ((size_t)b * Nn + slots_s[i]) * Nn + c0 + j0;
                #pragma unroll
                for (int q = 0; q < 4; q++) {
                    if (sq[q] < 0) {
                        __stcs(&out[base + q],           ap[q]);   // A_rec
                        __stcs(&out[MAT + base + q],     0.f);     // right
                        __stcs(&out[2 * MAT + base + q], dp[q]);   // D
                    }
                }
            }
        }
        __syncthreads();

        // colT publish (only non-R columns ever read; store all, cheap)
        for (int e = tid; e < 4096; e += 512) {
            int cc = e >> 6, rr = e & 63;
            g_DcolT[b][c0 + cc][rr] = Dsh[rr * SP + cc];
            g_AcolT[b][c0 + cc][rr] = Esh[rr * SP + cc];
        }
    }
}

// ---------------- KD: non-strip A_rec / D rows + flag reset -------------------
__global__ void __launch_bounds__(512) mmf_kd(const float* __restrict__ A,
                                              float* __restrict__ out) {
    // reset flags for next graph replay (mmf_ka has fully completed here)
    if (blockIdx.x == 0 && blockIdx.y == 0 && threadIdx.x < Bb) {
        g_flagM[threadIdx.x]  = 0;
        g_flagMT[threadIdx.x] = 0;
    }

    const int b    = blockIdx.y;
    const int i    = blockIdx.x * 4 + (threadIdx.x >> 7);
    const int lane = threadIdx.x & 127;
    const int c0   = lane * 4;

    if (g_slotof[b][i] >= 0) return;   // strip rows written in mmf_ka

    const size_t rowbase = ((size_t)b * Nn + i) * Nn + c0;
    const char4 sl = *(const char4*)(&g_slotof[b][c0]);

    float4 a = *(const float4*)&A[rowbase];   // L2-warm
    float4 va = a, vd = a;
    const float* act = &g_AcolT[b][i][0];
    const float* dct = &g_DcolT[b][i][0];
    if (sl.x >= 0) { va.x = act[sl.x]; vd.x = dct[sl.x]; }
    if (sl.y >= 0) { va.y = act[sl.y]; vd.y = dct[sl.y]; }
    if (sl.z >= 0) { va.z = act[sl.z]; vd.z = dct[sl.z]; }
    if (sl.w >= 0) { va.w = act[sl.w]; vd.w = dct[sl.w]; }

    const size_t MAT = (size_t)Bb * Nn * Nn;
    __stcs((float4*)&out[rowbase],           va);
    __stcs((float4*)&out[2 * MAT + rowbase], vd);
}

// ---------------- launch ------------------------------------------------------
extern "C" void kernel_launch(void* const* d_in, const int* in_sizes, int n_in,
                              void* d_out, int out_size) {
    const float* A   = (const float*)d_in[0];
    const float* O   = (const float*)d_in[1];
    const int*   idx = (const int*)d_in[2];
    const int*   wav = (const int*)d_in[3];
    float* out = (float*)d_out;

    cudaFuncSetAttribute(mmf_ka, cudaFuncAttributeMaxDynamicSharedMemorySize,
                         KF_SMEM);

    mmf_ka<<<KA_GRID, 512, KF_SMEM>>>(A, O, idx, wav, out);
    mmf_kd<<<dim3(Nn / 4, Bb), 512>>>(A, out);
}

// round 11
// speedup vs baseline: 1.2235x; 1.2235x over previous
#include <cuda_runtime.h>
#include <stdint.h>

#define Bb 32
#define Nn 512
#define Ll 8
#define Kk 8
#define MS 64
#define SP 68    // shared stride: conflict-free, 16B-aligned rows

// ---------------- scratch (static device globals) ---------------------------
__device__ float  g_MT[Bb][MS][MS];      // MT[i][j] = M[j][i]
__device__ float  g_P [Bb][MS][MS];      // M^T diag(~w) M (symmetric)
__device__ float  g_DRR[Bb][MS][MS];
__device__ float  g_G2[Bb][MS][MS];
__device__ float  g_DcolT[Bb][Nn][MS];   // strip D transposed (per column)
__device__ float  g_AcolT[Bb][Nn][MS];
__device__ int8_t g_slotof[Bb][Nn];
__device__ int    g_slots[Bb][MS];
__device__ int8_t g_wflag[Bb][128];      // padded per b
__device__ int    g_m[Bb][32];           // padded per b
__device__ int    g_flagM[Bb];           // maps ready
__device__ int    g_flagP[Bb];           // MT + P ready
__device__ int    g_flagA[Bb];           // DRR + G2 ready
__device__ float  g_sink;

// ---------------- packed f32x2 helpers --------------------------------------
typedef unsigned long long ull;

__device__ __forceinline__ ull pack2(float x) {
    ull r; asm("mov.b64 %0, {%1, %1};" : "=l"(r) : "f"(x)); return r;
}
__device__ __forceinline__ void ffma2(ull& d, ull a, ull b) {
    asm("fma.rn.f32x2 %0, %1, %2, %3;" : "=l"(d) : "l"(a), "l"(b), "l"(d));
}
__device__ __forceinline__ void unpack2(ull v, float& lo, float& hi) {
    asm("mov.b64 {%0, %1}, %2;" : "=f"(lo), "=f"(hi) : "l"(v));
}

// C = A @ B (64x64), 512 threads, 2 rows x 4 cols per thread.
__device__ __forceinline__ void gemmAT512(const float* __restrict__ AT,
                                          const float* __restrict__ Bsh,
                                          float* __restrict__ Csh, int tid) {
    const int i0 = (tid >> 4) * 2;
    const int j0 = (tid & 15) * 4;
    ull a00 = 0, a01 = 0, a10 = 0, a11 = 0;
    #pragma unroll 8
    for (int k = 0; k < 64; k++) {
        float2 aq = *(const float2*)&AT[k * SP + i0];
        ulonglong2 bq = *(const ulonglong2*)&Bsh[k * SP + j0];
        ull p0 = pack2(aq.x), p1 = pack2(aq.y);
        ffma2(a00, p0, bq.x); ffma2(a01, p0, bq.y);
        ffma2(a10, p1, bq.x); ffma2(a11, p1, bq.y);
    }
    ulonglong2 s0; s0.x = a00; s0.y = a01;
    ulonglong2 s1; s1.x = a10; s1.y = a11;
    *(ulonglong2*)&Csh[i0 * SP + j0]       = s0;
    *(ulonglong2*)&Csh[(i0 + 1) * SP + j0] = s1;
}

// ---------------- KA: roles A (setup) + C (strip tiles), all resident --------
#define KF_SMEM (5 * 64 * SP * 4)
#define NC_BASE 32
#define KA_GRID (NC_BASE + Bb * 8)   // 288 <= 296 resident slots

__global__ void __launch_bounds__(512, 2)
mmf_ka(const float* __restrict__ A, const float* __restrict__ O,
       const int* __restrict__ idx, const int* __restrict__ wav,
       float* __restrict__ out) {
    extern __shared__ float sm[];
    const int bid = blockIdx.x;
    const int tid = threadIdx.x;
    const size_t MAT = (size_t)Bb * Nn * Nn;

    // ======================= ROLE A: per-batch setup ========================
    if (bid < Bb) {
        float* Msh  = sm;
        float* MTsh = sm + 1 * 64 * SP;
        float* BufA = sm + 2 * 64 * SP;   // A_RR
        float* BufB = sm + 3 * 64 * SP;   // Y, then T
        float* BufC = sm + 4 * 64 * SP;   // D_RR

        __shared__ int   slotof[Nn];
        __shared__ int   slots[MS], val[MS], isf[MS], pslot[MS], wflag[MS];
        __shared__ float OshAll[Ll * MS];

        const int b   = bid;
        const int wid = tid >> 5;
        const int lid = tid & 31;

        slotof[tid] = -1;
        if (tid < MS) { wflag[tid] = 0; slots[tid] = 0; val[tid] = idx[b * MS + tid]; }
        OshAll[tid] = O[(size_t)(tid >> 6) * Bb * MS + (size_t)b * MS + (tid & 63)];
        for (int e = tid; e < 4096; e += 512) {
            int i = e >> 6, j = e & 63;
            Msh[i * SP + j] = (i == j) ? 1.f : 0.f;
        }
        __syncthreads();

        // dedup
        if (tid < MS) {
            const int v = val[tid];
            int fp = MS;
            #pragma unroll 8
            for (int q = MS - 1; q >= 0; q--) if (val[q] == v) fp = q;
            isf[tid] = (fp == tid) ? 1 : 0;
            pslot[tid] = fp;
        }
        __syncthreads();
        if (tid < MS) {
            const int fp = pslot[tid];
            int s = 0;
            #pragma unroll 8
            for (int q = 0; q < MS; q++) s += (q < fp) ? isf[q] : 0;
            pslot[tid] = s;
            if (isf[tid]) { slots[s] = val[tid]; slotof[val[tid]] = s; }
        }
        __syncthreads();
        if (tid < Ll) wflag[slotof[wav[b * Ll + tid]]] = 1;
        if (tid == 256) {
            int m = 0;
            #pragma unroll
            for (int q = 0; q < MS; q++) m += isf[q];
            g_m[b][0] = m;
        }
        __syncthreads();

        // publish maps -> flagM
        g_slotof[b][tid] = (int8_t)slotof[tid];
        if (tid < MS) {
            g_slots[b][tid] = slots[tid];
            g_wflag[b][tid] = (int8_t)wflag[tid];
        }
        __threadfence();
        __syncthreads();
        if (tid == 0) *(volatile int*)&g_flagM[b] = 1;

        // warp 0 builds M; warps 1-15 gather A_RR
        if (wid == 0) {
            for (int l = 0; l < Ll; l++) {
                int rsv[Kk];
                #pragma unroll
                for (int j = 0; j < Kk; j++) rsv[j] = pslot[l * Kk + j];
                float acc0[Kk], acc1[Kk];
                #pragma unroll
                for (int i = 0; i < Kk; i++) { acc0[i] = 0.f; acc1[i] = 0.f; }
                #pragma unroll
                for (int j = 0; j < Kk; j++) {
                    const float m0 = Msh[rsv[j] * SP + lid];
                    const float m1 = Msh[rsv[j] * SP + lid + 32];
                    #pragma unroll
                    for (int i = 0; i < Kk; i++) {
                        const float o = OshAll[l * MS + i * Kk + j];
                        acc0[i] += o * m0;
                        acc1[i] += o * m1;
                    }
                }
                __syncwarp();
                #pragma unroll
                for (int i = 0; i < Kk; i++) {
                    Msh[rsv[i] * SP + lid]      = acc0[i];
                    Msh[rsv[i] * SP + lid + 32] = acc1[i];
                }
                __syncwarp();
            }
        } else {
            const int t = tid - 32;
            for (int e = t; e < 4096; e += 480) {
                int i = e >> 6, j = e & 63;
                BufA[i * SP + j] = A[((size_t)b * Nn + slots[i]) * Nn + slots[j]];
            }
        }
        __syncthreads();

        // transpose + publish MT
        for (int e = tid; e < 4096; e += 512) {
            int i = e >> 6, j = e & 63;
            MTsh[j * SP + i] = Msh[i * SP + j];
        }
        __syncthreads();
        for (int e = tid; e < 4096; e += 512)
            g_MT[b][e >> 6][e & 63] = MTsh[(e >> 6) * SP + (e & 63)];

        // P = M^T diag(~w) M  (predicated A operand) -> g_P, then flagP
        {
            const int i0 = (tid >> 4) * 2;
            const int j0 = (tid & 15) * 4;
            ull y00 = 0, y01 = 0, y10 = 0, y11 = 0;
            #pragma unroll 8
            for (int k = 0; k < 64; k++) {
                const bool wz = (wflag[k] != 0);
                float2 cq = *(const float2*)&Msh[k * SP + i0];
                ulonglong2 bq = *(const ulonglong2*)&Msh[k * SP + j0];
                ull q0 = wz ? 0ULL : pack2(cq.x);
                ull q1 = wz ? 0ULL : pack2(cq.y);
                ffma2(y00, q0, bq.x); ffma2(y01, q0, bq.y);
                ffma2(y10, q1, bq.x); ffma2(y11, q1, bq.y);
            }
            float4 w0, w1;
            unpack2(y00, w0.x, w0.y); unpack2(y01, w0.z, w0.w);
            unpack2(y10, w1.x, w1.y); unpack2(y11, w1.z, w1.w);
            *(float4*)&g_P[b][i0][j0]     = w0;
            *(float4*)&g_P[b][i0 + 1][j0] = w1;
        }
        __threadfence();
        __syncthreads();
        if (tid == 0) *(volatile int*)&g_flagP[b] = 1;

        // S1: Y = A_RR @ M^T (A_RR symmetric -> AT = BufA; B = MTsh)
        gemmAT512(BufA, MTsh, BufB, tid);  __syncthreads();

        // S2: F = M @ Y, mask fused -> BufC (=D_RR) + publish g_DRR
        {
            const int i0 = (tid >> 4) * 2;
            const int j0 = (tid & 15) * 4;
            ull a00 = 0, a01 = 0, a10 = 0, a11 = 0;
            #pragma unroll 8
            for (int k = 0; k < 64; k++) {
                float2 aq = *(const float2*)&MTsh[k * SP + i0];
                ulonglong2 bq = *(const ulonglong2*)&BufB[k * SP + j0];
                ull p0 = pack2(aq.x), p1 = pack2(aq.y);
                ffma2(a00, p0, bq.x); ffma2(a01, p0, bq.y);
                ffma2(a10, p1, bq.x); ffma2(a11, p1, bq.y);
            }
            float f[2][4];
            unpack2(a00, f[0][0], f[0][1]); unpack2(a01, f[0][2], f[0][3]);
            unpack2(a10, f[1][0], f[1][1]); unpack2(a11, f[1][2], f[1][3]);
            #pragma unroll
            for (int r = 0; r < 2; r++) {
                const int i = i0 + r;
                float4 dv;
                float* dp = (float*)&dv;
                #pragma unroll
                for (int q = 0; q < 4; q++) {
                    const int j = j0 + q;
                    float v = f[r][q];
                    if (i != j && (wflag[i] || wflag[j])) v = 0.f;
                    dp[q] = v;
                }
                *(float4*)&BufC[i * SP + j0] = dv;
                *(float4*)&g_DRR[b][i][j0]  = dv;
            }
        }
        __syncthreads();

        // S3: T = D @ M (D symmetric -> AT = BufC; B = Msh) -> BufB
        gemmAT512(BufC, Msh, BufB, tid);  __syncthreads();

        // S4: G2 = M^T @ T -> g_G2, then flagA
        {
            const int i0 = (tid >> 4) * 2;
            const int j0 = (tid & 15) * 4;
            ull a00 = 0, a01 = 0, a10 = 0, a11 = 0;
            #pragma unroll 8
            for (int k = 0; k < 64; k++) {
                float2 aq = *(const float2*)&Msh[k * SP + i0];
                ulonglong2 bq = *(const ulonglong2*)&BufB[k * SP + j0];
                ull p0 = pack2(aq.x), p1 = pack2(aq.y);
                ffma2(a00, p0, bq.x); ffma2(a01, p0, bq.y);
                ffma2(a10, p1, bq.x); ffma2(a11, p1, bq.y);
            }
            float4 w0, w1;
            unpack2(a00, w0.x, w0.y); unpack2(a01, w0.z, w0.w);
            unpack2(a10, w1.x, w1.y); unpack2(a11, w1.z, w1.w);
            *(float4*)&g_G2[b][i0][j0]     = w0;
            *(float4*)&g_G2[b][i0 + 1][j0] = w1;
        }
        __threadfence();
        __syncthreads();
        if (tid == 0) *(volatile int*)&g_flagA[b] = 1;
        return;
    }

    // ================== ROLE C: strip tiles ==================================
    {
        float* MTsh = sm;
        float* Psh  = sm + 1 * 64 * SP;
        float* At   = sm + 2 * 64 * SP;
        float* Dsh  = sm + 3 * 64 * SP;
        float* Esh  = sm + 4 * 64 * SP;

        __shared__ int    slots_s[MS];
        __shared__ int8_t wfl[MS];
        __shared__ int8_t slrow[MS];
        __shared__ int    mS;

        const int t  = bid - NC_BASE;
        const int b  = t >> 3;
        const int c0 = (t & 7) << 6;

        // wait for maps
        if (tid == 0) { while (*(volatile int*)&g_flagM[b] == 0) __nanosleep(100); }
        __syncthreads();
        __threadfence();

        if (tid < MS) {
            slots_s[tid] = g_slots[b][tid];
            slrow[tid]   = g_slotof[b][c0 + tid];
            wfl[tid]     = g_wflag[b][tid];
        }
        if (tid == 0) mS = g_m[b][0];
        __syncthreads();

        // --- overlap with role A: gather tile, right-identity, A->L2 prefetch
        for (int e = tid; e < 4096; e += 512) {
            int k = e >> 6, c = e & 63;
            At[k * SP + c] = A[((size_t)b * Nn + slots_s[k]) * Nn + c0 + c];
        }
        {
            float acc = 0.f;
            for (int it = 0; it < 16; it++) {
                const int e = it * 512 + tid;
                const int r = e >> 7, lane = e & 127;
                const int i = c0 + r, cc0 = lane * 4;
                const size_t rowbase = ((size_t)b * Nn + i) * Nn + cc0;
                float4 a = __ldg((const float4*)&A[rowbase]);   // warm L2
                acc += a.x + a.w;
                if (slrow[r] < 0) {
                    float4 vr = make_float4(0.f, 0.f, 0.f, 0.f);
                    if (i >= cc0 && i < cc0 + 4) ((float*)&vr)[i - cc0] = 1.f;
                    __stcs((float4*)&out[MAT + rowbase], vr);
                }
            }
            if (acc == 1e38f) g_sink = acc;
        }

        // wait for MT + P, then run the heavy dual GEMM (overlaps A's S1-S4)
        if (tid == 0) { while (*(volatile int*)&g_flagP[b] == 0) __nanosleep(100); }
        __syncthreads();
        __threadfence();

        for (int e = tid; e < 4096; e += 512) {
            int i = e >> 6, j = e & 63;
            MTsh[i * SP + j] = g_MT[b][i][j];
            Psh[i * SP + j]  = g_P[b][i][j];
        }
        __syncthreads();

        const int i0 = (tid >> 4) * 2;
        const int j0 = (tid & 15) * 4;
        ull x00 = 0, x01 = 0, x10 = 0, x11 = 0;
        ull y00 = 0, y01 = 0, y10 = 0, y11 = 0;
        #pragma unroll 4
        for (int k = 0; k < 64; k++) {
            float2 mq = *(const float2*)&MTsh[k * SP + i0];
            float2 pq = *(const float2*)&Psh[k * SP + i0];
            ulonglong2 bq = *(const ulonglong2*)&At[k * SP + j0];
            ull m0 = pack2(mq.x), m1 = pack2(mq.y);
            ull p0 = pack2(pq.x), p1 = pack2(pq.y);
            ffma2(x00, m0, bq.x); ffma2(x01, m0, bq.y);
            ffma2(x10, m1, bq.x); ffma2(x11, m1, bq.y);
            ffma2(y00, p0, bq.x); ffma2(y01, p0, bq.y);
            ffma2(y10, p1, bq.x); ffma2(y11, p1, bq.y);
        }

        // wait for substitution tables (DRR, G2)
        if (tid == 0) { while (*(volatile int*)&g_flagA[b] == 0) __nanosleep(100); }
        __syncthreads();
        __threadfence();

        const int s0 = slrow[j0], s1 = slrow[j0 + 1];
        const int s2 = slrow[j0 + 2], s3 = slrow[j0 + 3];
        float f[2][4], e2[2][4];
        unpack2(x00, f[0][0], f[0][1]); unpack2(x01, f[0][2], f[0][3]);
        unpack2(x10, f[1][0], f[1][1]); unpack2(x11, f[1][2], f[1][3]);
        unpack2(y00, e2[0][0], e2[0][1]); unpack2(y01, e2[0][2], e2[0][3]);
        unpack2(y10, e2[1][0], e2[1][1]); unpack2(y11, e2[1][2], e2[1][3]);

        #pragma unroll
        for (int r = 0; r < 2; r++) {
            const int i = i0 + r;
            const float wz = wfl[i] ? 0.f : 1.f;
            float4 dv, av, rv;
            dv.x = (s0 >= 0) ? g_DRR[b][i][s0] : wz * f[r][0];
            dv.y = (s1 >= 0) ? g_DRR[b][i][s1] : wz * f[r][1];
            dv.z = (s2 >= 0) ? g_DRR[b][i][s2] : wz * f[r][2];
            dv.w = (s3 >= 0) ? g_DRR[b][i][s3] : wz * f[r][3];
            av.x = (s0 >= 0) ? g_G2[b][i][s0] : e2[r][0];
            av.y = (s1 >= 0) ? g_G2[b][i][s1] : e2[r][1];
            av.z = (s2 >= 0) ? g_G2[b][i][s2] : e2[r][2];
            av.w = (s3 >= 0) ? g_G2[b][i][s3] : e2[r][3];
            rv.x = (s0 >= 0) ? MTsh[s0 * SP + i] : 0.f;
            rv.y = (s1 >= 0) ? MTsh[s1 * SP + i] : 0.f;
            rv.z = (s2 >= 0) ? MTsh[s2 * SP + i] : 0.f;
            rv.w = (s3 >= 0) ? MTsh[s3 * SP + i] : 0.f;

            *(float4*)&Dsh[i * SP + j0] = dv;
            *(float4*)&Esh[i * SP + j0] = av;
            if (i < mS) {
                const size_t base = ((size_t)b * Nn + slots_s[i]) * Nn + c0 + j0;
                __stcs((float4*)&out[base],           av);
                __stcs((float4*)&out[MAT + base],     rv);
                __stcs((float4*)&out[2 * MAT + base], dv);
            }
        }
        __syncthreads();

        // colT publish (L2-resident for KD)
        for (int e = tid; e < 4096; e += 512) {
            int cc = e >> 6, rr = e & 63;
            g_DcolT[b][c0 + cc][rr] = Dsh[rr * SP + cc];
            g_AcolT[b][c0 + cc][rr] = Esh[rr * SP + cc];
        }
    }
}

// ---------------- KD: non-strip A_rec / D rows + flag reset -------------------
__global__ void __launch_bounds__(512) mmf_kd(const float* __restrict__ A,
                                              float* __restrict__ out) {
    // reset flags for next graph replay (mmf_ka fully completed before kd runs)
    if (blockIdx.x == 0 && blockIdx.y == 0 && threadIdx.x < Bb) {
        g_flagM[threadIdx.x] = 0;
        g_flagP[threadIdx.x] = 0;
        g_flagA[threadIdx.x] = 0;
    }

    const int b    = blockIdx.y;
    const int i    = blockIdx.x * 4 + (threadIdx.x >> 7);
    const int lane = threadIdx.x & 127;
    const int c0   = lane * 4;

    if (g_slotof[b][i] >= 0) return;   // strip rows written by role C

    const size_t rowbase = ((size_t)b * Nn + i) * Nn + c0;
    const char4 sl = *(const char4*)(&g_slotof[b][c0]);

    float4 a = *(const float4*)&A[rowbase];   // L2-warm
    float4 va = a, vd = a;
    const float* act = &g_AcolT[b][i][0];
    const float* dct = &g_DcolT[b][i][0];
    if (sl.x >= 0) { va.x = act[sl.x]; vd.x = dct[sl.x]; }
    if (sl.y >= 0) { va.y = act[sl.y]; vd.y = dct[sl.y]; }
    if (sl.z >= 0) { va.z = act[sl.z]; vd.z = dct[sl.z]; }
    if (sl.w >= 0) { va.w = act[sl.w]; vd.w = dct[sl.w]; }

    const size_t MAT = (size_t)Bb * Nn * Nn;
    __stcs((float4*)&out[rowbase],           va);
    __stcs((float4*)&out[2 * MAT + rowbase], vd);
}

// ---------------- launch ------------------------------------------------------
extern "C" void kernel_launch(void* const* d_in, const int* in_sizes, int n_in,
                              void* d_out, int out_size) {
    const float* A   = (const float*)d_in[0];
    const float* O   = (const float*)d_in[1];
    const int*   idx = (const int*)d_in[2];
    const int*   wav = (const int*)d_in[3];
    float* out = (float*)d_out;

    cudaFuncSetAttribute(mmf_ka, cudaFuncAttributeMaxDynamicSharedMemorySize,
                         KF_SMEM);

    mmf_ka<<<KA_GRID, 512, KF_SMEM>>>(A, O, idx, wav, out);
    mmf_kd<<<dim3(Nn / 4, Bb), 512>>>(A, out);
}